// round 8
// baseline (speedup 1.0000x reference)
#include <cuda_runtime.h>
#include <cuda_fp16.h>
#include <cstdint>
#include <math.h>

#define ALPHA_C 0.5f
#define EPS_C   0.01f
#define NBd 4096
#define NXd 512
#define NYd 256
#define NUd 256
#define NQd 256
#define NXQ 768

#define TBK 32
#define SROWH 40   // smem row stride in halves (80B): LDSM conflict-free

// ---------------- device scratch ----------------
__device__ float g_H[NXQ * NXQ];
__device__ float g_Pi[NXd * NXd];
__device__ float g_MmT[NXd * NXd];
__device__ float g_NmT[NQd * NXd];
__device__ float g_laminv[NQd];
__device__ float g_D11T[NQd * NQd];
__device__ float g_C1[NQd * NXd];
__device__ float g_BigB0[(NXd + NYd) * NXd];   // [A ; C2]   768 x 512
__device__ float g_BigB1[(NXd + NYd) * NQd];   // [B1 ; D21] 768 x 256
__device__ float g_BigB2[(NXd + NYd) * NUd];   // [B2 ; D22] 768 x 256
__device__ float g_a[NBd * NQd];
__device__ float g_w[NBd * NQd];

__device__ __forceinline__ void mma_f16(float c[4], const uint32_t a[4], const uint32_t b[2]) {
    asm volatile(
        "mma.sync.aligned.m16n8k16.row.col.f32.f16.f16.f32 "
        "{%0,%1,%2,%3}, {%4,%5,%6,%7}, {%8,%9}, {%0,%1,%2,%3};"
        : "+f"(c[0]), "+f"(c[1]), "+f"(c[2]), "+f"(c[3])
        : "r"(a[0]), "r"(a[1]), "r"(a[2]), "r"(a[3]), "r"(b[0]), "r"(b[1]));
}
__device__ __forceinline__ void ldsm_x4(uint32_t r[4], uint32_t addr) {
    asm volatile("ldmatrix.sync.aligned.m8n8.x4.shared.b16 {%0,%1,%2,%3}, [%4];"
        : "=r"(r[0]), "=r"(r[1]), "=r"(r[2]), "=r"(r[3]) : "r"(addr));
}
__device__ __forceinline__ uint32_t h2pack(float lo, float hi) {
    __half2 h = __floats2half2_rn(lo, hi);
    return *(uint32_t*)&h;
}

// ---------------- pipelined fp16 mma.sync NT GEMM (template) ----------------
// C = sum_seg Aseg[M][Ks] @ Bseg[N][Ks]^T  (+ diagAdd on i==j)
// fp32 gmem -> half smem (double-buffered), m16n8k16 fp16 MMA, fp32 accum.
template<int TBM_, int WM_, int WN_>
__global__ void __launch_bounds__(WM_ * WN_ * 32) gemm_tc_t(
    const float* __restrict__ A0, const float* __restrict__ B0, int K0,
    const float* __restrict__ A1, const float* __restrict__ B1p, int K1,
    const float* __restrict__ A2, const float* __restrict__ B2p, int K2,
    float* __restrict__ C0, int N0, float* __restrict__ C1, int N1, int NSPLIT,
    float diagAdd)
{
    constexpr int THREADS = WM_ * WN_ * 32;
    constexpr int IM = TBM_ / WM_ / 16;
    constexpr int IN = TBM_ / WN_ / 8;
    constexpr int IP = IN / 2;
    constexpr int SZH = TBM_ * SROWH;              // halves per buffer
    static_assert(THREADS == 2 * TBM_, "loader mapping needs threads == 2*TBM");
    static_assert((IN & 1) == 0, "IN must be even");

    extern __shared__ __half smem[];
    __half* sA = smem;              // [2][SZH]
    __half* sB = smem + 2 * SZH;    // [2][SZH]

    const int tid  = threadIdx.x;
    const int wid  = tid >> 5;
    const int lane = tid & 31;
    const int g    = lane >> 2;
    const int tig  = lane & 3;
    const int bm = blockIdx.y * TBM_;
    const int bn = blockIdx.x * TBM_;
    const int wm = (wid % WM_) * (TBM_ / WM_);
    const int wn = (wid / WM_) * (TBM_ / WN_);
    const int lrow = tid >> 1;
    const int lcol = (tid & 1) * 16;               // halves offset (16 elems)

    const uint32_t sA_addr = (uint32_t)__cvta_generic_to_shared(sA);
    const uint32_t sB_addr = (uint32_t)__cvta_generic_to_shared(sB);
    // x4 mapping: lanes 0-15 -> rows (lane&15) at k0; lanes 16-31 -> same rows at k+8
    uint32_t a_base[IM], b_base[IP];
#pragma unroll
    for (int im = 0; im < IM; ++im)
        a_base[im] = sA_addr +
            (((wm + 16 * im + (lane & 15)) * SROWH + 8 * (lane >> 4)) << 1);
#pragma unroll
    for (int p = 0; p < IP; ++p)
        b_base[p] = sB_addr +
            (((wn + 16 * p + (lane & 15)) * SROWH + 8 * (lane >> 4)) << 1);

    float acc[IM][IN][4];
#pragma unroll
    for (int i = 0; i < IM; ++i)
#pragma unroll
        for (int j = 0; j < IN; ++j)
#pragma unroll
            for (int q = 0; q < 4; ++q) acc[i][j][q] = 0.f;

    const int nch0 = K0 / TBK, nch1 = K1 / TBK, nch2 = K2 / TBK;
    const int nch = nch0 + nch1 + nch2;

    float4 ra[4], rb[4];
    const float* Ap = A0; const float* Bp = B0; int Kk = K0; int k0 = 0;

    auto getc = [&](int c) {
        if (c < nch0)              { Ap = A0; Bp = B0;  Kk = K0; k0 = c * TBK; }
        else if (c < nch0 + nch1)  { Ap = A1; Bp = B1p; Kk = K1; k0 = (c - nch0) * TBK; }
        else                       { Ap = A2; Bp = B2p; Kk = K2; k0 = (c - nch0 - nch1) * TBK; }
    };
    auto ldg = [&]() {
        const float* ap = Ap + (size_t)(bm + lrow) * Kk + k0 + lcol;
        const float* bp = Bp + (size_t)(bn + lrow) * Kk + k0 + lcol;
#pragma unroll
        for (int q = 0; q < 4; ++q) { ra[q] = *(const float4*)(ap + 4 * q); }
#pragma unroll
        for (int q = 0; q < 4; ++q) { rb[q] = *(const float4*)(bp + 4 * q); }
    };
    auto sts = [&](int b) {
        __half* dA = sA + b * SZH + lrow * SROWH + lcol;
        __half* dB = sB + b * SZH + lrow * SROWH + lcol;
        uint4 pa = make_uint4(h2pack(ra[0].x, ra[0].y), h2pack(ra[0].z, ra[0].w),
                              h2pack(ra[1].x, ra[1].y), h2pack(ra[1].z, ra[1].w));
        uint4 pa2 = make_uint4(h2pack(ra[2].x, ra[2].y), h2pack(ra[2].z, ra[2].w),
                               h2pack(ra[3].x, ra[3].y), h2pack(ra[3].z, ra[3].w));
        uint4 pb = make_uint4(h2pack(rb[0].x, rb[0].y), h2pack(rb[0].z, rb[0].w),
                              h2pack(rb[1].x, rb[1].y), h2pack(rb[1].z, rb[1].w));
        uint4 pb2 = make_uint4(h2pack(rb[2].x, rb[2].y), h2pack(rb[2].z, rb[2].w),
                               h2pack(rb[3].x, rb[3].y), h2pack(rb[3].z, rb[3].w));
        *(uint4*)(dA)     = pa;
        *(uint4*)(dA + 8) = pa2;
        *(uint4*)(dB)     = pb;
        *(uint4*)(dB + 8) = pb2;
    };
    auto comp = [&](int b) {
        const uint32_t boff = (uint32_t)(b * SZH * 2);
#pragma unroll
        for (int k16 = 0; k16 < TBK; k16 += 16) {
            uint32_t afr[IM][4];
            uint32_t bfr[IN][2];
#pragma unroll
            for (int im = 0; im < IM; ++im)
                ldsm_x4(afr[im], a_base[im] + boff + (k16 << 1));
#pragma unroll
            for (int p = 0; p < IP; ++p) {
                uint32_t t[4];
                ldsm_x4(t, b_base[p] + boff + (k16 << 1));
                bfr[2 * p][0] = t[0]; bfr[2 * p + 1][0] = t[1];
                bfr[2 * p][1] = t[2]; bfr[2 * p + 1][1] = t[3];
            }
#pragma unroll
            for (int im = 0; im < IM; ++im)
#pragma unroll
                for (int in_ = 0; in_ < IN; ++in_)
                    mma_f16(acc[im][in_], afr[im], bfr[in_]);
        }
    };

    getc(0); ldg(); sts(0);
    __syncthreads();
    for (int c = 0; c < nch; ++c) {
        if (c + 1 < nch) { getc(c + 1); ldg(); }
        comp(c & 1);
        if (c + 1 < nch) { sts((c + 1) & 1); }
        __syncthreads();
    }

    // ---- epilogue with split output ----
#pragma unroll
    for (int im = 0; im < IM; ++im) {
#pragma unroll
        for (int in_ = 0; in_ < IN; ++in_) {
            int row0 = bm + wm + 16 * im + g;
            int col0 = bn + wn + 8 * in_ + 2 * tig;
            float c0 = acc[im][in_][0], c1 = acc[im][in_][1];
            float c2 = acc[im][in_][2], c3 = acc[im][in_][3];
            if (diagAdd != 0.f) {
                if (row0 == col0)         c0 += diagAdd;
                if (row0 == col0 + 1)     c1 += diagAdd;
                if (row0 + 8 == col0)     c2 += diagAdd;
                if (row0 + 8 == col0 + 1) c3 += diagAdd;
            }
            float* base; int st; int cc = col0;
            if (col0 >= NSPLIT) { base = C1; st = N1; cc = col0 - NSPLIT; }
            else                { base = C0; st = N0; }
            *(float2*)(base + (size_t)row0 * st + cc)       = make_float2(c0, c1);
            *(float2*)(base + (size_t)(row0 + 8) * st + cc) = make_float2(c2, c3);
        }
    }
}

// ---------------- frame elementwise builders ----------------
__global__ void build_MN_kernel(const float* __restrict__ S, const float* __restrict__ U)
{
    int idx = blockIdx.x * blockDim.x + threadIdx.x;
    if (idx < NXd * NXd) {
        int j = idx / NXd, n = idx - j * NXd;
        g_MmT[idx] = -0.5f * g_H[n * NXQ + j] - S[n * NXd + j] + S[j * NXd + n];
    } else if (idx < NXd * NXd + NQd * NXd) {
        int idx2 = idx - NXd * NXd;
        int j = idx2 / NXd, n = idx2 - j * NXd;
        g_NmT[idx2] = -(g_H[n * NXQ + NXd + j] + U[n * NQd + j]);
    } else {
        int k = idx - NXd * NXd - NQd * NXd;
        if (k < NQd) g_laminv[k] = 2.0f / g_H[(NXd + k) * NXQ + NXd + k];
    }
}

__global__ void build_DC_kernel(const float* __restrict__ U)
{
    int idx = blockIdx.x * blockDim.x + threadIdx.x;
    if (idx < NQd * NQd) {
        int j = idx / NQd, k = idx - j * NQd;
        g_D11T[idx] = (j < k) ? (-g_H[(NXd + k) * NXQ + NXd + j] * g_laminv[k]) : 0.f;
    } else {
        int idx2 = idx - NQd * NQd;
        if (idx2 < NQd * NXd) {
            int k = idx2 / NXd, i = idx2 - k * NXd;
            g_C1[idx2] = U[i * NQd + k] * g_laminv[k];
        }
    }
}

// ---------------- sequential triangular tanh solve ----------------
__global__ __launch_bounds__(256, 1) void solve_w_kernel()
{
    __shared__ float s_laminv[NQd];
    const int tid = threadIdx.x;
    s_laminv[tid] = g_laminv[tid];
    __syncthreads();

    const int c   = tid & 7;
    const int r   = tid >> 3;
    const int row = blockIdx.x * 32 + r;

    float acc[32];
    float wreg[32];

    const float* arow = g_a + row * NQd + c * 32;
#pragma unroll
    for (int i4 = 0; i4 < 8; ++i4) {
        float4 v = *(const float4*)(arow + 4 * i4);
        acc[4 * i4 + 0] = v.x; acc[4 * i4 + 1] = v.y;
        acc[4 * i4 + 2] = v.z; acc[4 * i4 + 3] = v.w;
    }

    for (int b = 0; b < 8; ++b) {
        const bool after = (c > b);
        const bool owner = (c == b);
#pragma unroll
        for (int jc = 0; jc < 32; ++jc) {
            const int j = (b << 5) + jc;
            float v  = acc[jc] * s_laminv[j];
            float ex = __expf(v + v);
            float wj = 1.f - __fdividef(2.f, ex + 1.f);
            wj = __shfl_sync(0xffffffffu, wj, b, 8);
            if (owner) wreg[jc] = wj;

            const float* drow = g_D11T + j * NQd + c * 32;
#pragma unroll
            for (int i4 = 0; i4 < 8; ++i4) {
                bool anyp = after || (owner && (4 * i4 + 3) > jc);
                float4 d = make_float4(0.f, 0.f, 0.f, 0.f);
                if (anyp) d = *(const float4*)(drow + 4 * i4);
                if (after || (owner && (4 * i4 + 0) > jc)) acc[4 * i4 + 0] = fmaf(wj, d.x, acc[4 * i4 + 0]);
                if (after || (owner && (4 * i4 + 1) > jc)) acc[4 * i4 + 1] = fmaf(wj, d.y, acc[4 * i4 + 1]);
                if (after || (owner && (4 * i4 + 2) > jc)) acc[4 * i4 + 2] = fmaf(wj, d.z, acc[4 * i4 + 2]);
                if (after || (owner && (4 * i4 + 3) > jc)) acc[4 * i4 + 3] = fmaf(wj, d.w, acc[4 * i4 + 3]);
            }
        }
    }

    float* wrow = g_w + row * NQd + c * 32;
#pragma unroll
    for (int i4 = 0; i4 < 8; ++i4) {
        *(float4*)(wrow + 4 * i4) =
            make_float4(wreg[4 * i4 + 0], wreg[4 * i4 + 1], wreg[4 * i4 + 2], wreg[4 * i4 + 3]);
    }
}

// ---------------- launch ----------------
extern "C" void kernel_launch(void* const* d_in, const int* in_sizes, int n_in,
                              void* d_out, int out_size)
{
    const float* u_in  = (const float*)d_in[0];
    const float* x_in  = (const float*)d_in[1];
    const float* X_in  = (const float*)d_in[2];
    const float* S_in  = (const float*)d_in[3];
    const float* Pv_in = (const float*)d_in[4];
    const float* U_in  = (const float*)d_in[5];
    const float* D12   = (const float*)d_in[6];
    const float* B2    = (const float*)d_in[7];
    const float* C2    = (const float*)d_in[8];
    const float* D21   = (const float*)d_in[9];
    const float* D22   = (const float*)d_in[10];

    float* out = (float*)d_out;
    float* dx  = out;
    float* y   = out + (size_t)NBd * NXd;

    float *H, *Pi, *MmT, *NmT, *C1, *BB0, *BB1, *BB2, *a, *w;
    cudaGetSymbolAddress((void**)&H,   g_H);
    cudaGetSymbolAddress((void**)&Pi,  g_Pi);
    cudaGetSymbolAddress((void**)&MmT, g_MmT);
    cudaGetSymbolAddress((void**)&NmT, g_NmT);
    cudaGetSymbolAddress((void**)&C1,  g_C1);
    cudaGetSymbolAddress((void**)&BB0, g_BigB0);
    cudaGetSymbolAddress((void**)&BB1, g_BigB1);
    cudaGetSymbolAddress((void**)&BB2, g_BigB2);
    cudaGetSymbolAddress((void**)&a,   g_a);
    cudaGetSymbolAddress((void**)&w,   g_w);

    auto Big   = gemm_tc_t<128, 2, 4>;
    auto Small = gemm_tc_t<64, 2, 2>;
    const int SMEM_BIG   = 4 * 128 * SROWH * 2;   // 40960 B
    const int SMEM_SMALL = 4 * 64 * SROWH * 2;    // 20480 B
    cudaFuncSetAttribute(Big,   cudaFuncAttributeMaxDynamicSharedMemorySize, SMEM_BIG);
    cudaFuncSetAttribute(Small, cudaFuncAttributeMaxDynamicSharedMemorySize, SMEM_SMALL);

    const int NOSPLIT = 1 << 30;

    // (1) H = X X^T + eps I   (768x768, K=768)
    Small<<<dim3(NXQ / 64, NXQ / 64), 128, SMEM_SMALL>>>(
        X_in, X_in, NXQ, nullptr, nullptr, 0, nullptr, nullptr, 0,
        H, NXQ, nullptr, 0, NOSPLIT, EPS_C);

    // (2) MmT, NmT, laminv
    build_MN_kernel<<<(NXd * NXd + NQd * NXd + NQd + 255) / 256, 256>>>(S_in, U_in);

    // (3) D11T, C1
    build_DC_kernel<<<(NQd * NQd + NQd * NXd + 255) / 256, 256>>>(U_in);

    // (4) a = x C1^T + u D12^T  (4096x256)  <-- ncu-profiled slot
    Small<<<dim3(NQd / 64, NBd / 64), 128, SMEM_SMALL>>>(
        x_in, C1, NXd, u_in, D12, NQd, nullptr, nullptr, 0,
        a, NQd, nullptr, 0, NOSPLIT, 0.f);

    // (5) Pi = P_inv P_inv^T  (512x512)
    Small<<<dim3(NXd / 64, NXd / 64), 128, SMEM_SMALL>>>(
        Pv_in, Pv_in, NXd, nullptr, nullptr, 0, nullptr, nullptr, 0,
        Pi, NXd, nullptr, 0, NOSPLIT, 0.f);

    // (6) A = Pi @ M - alpha I  -> BigB0 rows 0..511
    Small<<<dim3(NXd / 64, NXd / 64), 128, SMEM_SMALL>>>(
        Pi, MmT, NXd, nullptr, nullptr, 0, nullptr, nullptr, 0,
        BB0, NXd, nullptr, 0, NOSPLIT, -ALPHA_C);

    // (7) B1 = Pi @ N  -> BigB1 rows 0..511
    Small<<<dim3(NQd / 64, NXd / 64), 128, SMEM_SMALL>>>(
        Pi, NmT, NXd, nullptr, nullptr, 0, nullptr, nullptr, 0,
        BB1, NQd, nullptr, 0, NOSPLIT, 0.f);

    // concat tails: [A;C2], [B1;D21], [B2;D22]
    cudaMemcpyAsync(BB0 + (size_t)NXd * NXd, C2,  (size_t)NYd * NXd * 4, cudaMemcpyDeviceToDevice);
    cudaMemcpyAsync(BB1 + (size_t)NXd * NQd, D21, (size_t)NYd * NQd * 4, cudaMemcpyDeviceToDevice);
    cudaMemcpyAsync(BB2,                     B2,  (size_t)NXd * NUd * 4, cudaMemcpyDeviceToDevice);
    cudaMemcpyAsync(BB2 + (size_t)NXd * NUd, D22, (size_t)NYd * NUd * 4, cudaMemcpyDeviceToDevice);

    // (8) sequential tanh solve -> w
    solve_w_kernel<<<NBd / 32, 256>>>();

    // (9) [dx | y] = x [A;C2]^T + w [B1;D21]^T + u [B2;D22]^T  (4096x768)
    Big<<<dim3((NXd + NYd) / 128, NBd / 128), 256, SMEM_BIG>>>(
        x_in, BB0, NXd, w, BB1, NQd, u_in, BB2, NUd,
        dx, NXd, y, NYd, NXd, 0.f);

    (void)in_sizes; (void)n_in; (void)out_size;
}